// round 7
// baseline (speedup 1.0000x reference)
#include <cuda_runtime.h>
#include <math.h>
#include <stdint.h>

#define N_PAT 4096
#define DIM   256
#define EPSV  1e-8f
#define RBLK  32                  // rows per prep block
#define NRB   (N_PAT / RBLK)      // 128 row-blocks per modality
#define NPREP (4 * NRB)           // 512 prep blocks
#define NCOX  (N_PAT / 16)        // 256 cox blocks (16 rows each)

// ---------------- static scratch ----------------
// transposed: [mod*256 + col][rb]  -> finish reads 512B contiguous per column
__device__ float  g_uT[4 * DIM * NRB];
__device__ float2 g_vw[NPREP];            // per (mod,rowblock) (V,W)
__device__ float  g_coxpart[N_PAT];

// ---------------- kernel 1: fused prep + cox ----------------
__global__ void __launch_bounds__(256)
main_kernel(const float* __restrict__ h, const int* __restrict__ t,
            const int* __restrict__ e,
            const float* __restrict__ eb0, const float* __restrict__ eb1,
            const float* __restrict__ eb2, const float* __restrict__ eb3) {
    __shared__ float smf[2048];     // prep: [8 warps][256 cols] | cox: se[1024]
    __shared__ int   smi[1024];     // cox: st
    __shared__ float snm[8], sww[8];

    int tid = threadIdx.x;

    if (blockIdx.x < NPREP) {
        // ================= prep block =================
        int mod = blockIdx.x >> 7;
        int rb  = blockIdx.x & 127;
        int r0  = rb * RBLK;
        const float* base = (mod == 0) ? eb0 : (mod == 1) ? eb1
                          : (mod == 2) ? eb2 : eb3;
        int w = tid >> 5, lane = tid & 31;

        // load 4 rows x 2 float4 per lane, all independent (MLP = 8)
        float4 va[4], vb[4];
#pragma unroll
        for (int rr = 0; rr < 4; rr++) {
            const float4* src = (const float4*)(base + (size_t)(r0 + w * 4 + rr) * DIM);
            va[rr] = src[lane];
            vb[rr] = src[lane + 32];
        }

        float4 acc0 = make_float4(0.f, 0.f, 0.f, 0.f);
        float4 acc1 = make_float4(0.f, 0.f, 0.f, 0.f);
        float nmW = 0.0f, wW = 0.0f;
#pragma unroll
        for (int rr = 0; rr < 4; rr++) {
            float4 v0 = va[rr], v1 = vb[rr];
            float x0 = __shfl_sync(0xffffffffu, v0.x, 0);
            bool eq = (v0.x == x0) && (v0.y == x0) && (v0.z == x0) && (v0.w == x0) &&
                      (v1.x == x0) && (v1.y == x0) && (v1.z == x0) && (v1.w == x0);
            bool miss = (__ballot_sync(0xffffffffu, eq) == 0xffffffffu);

            float ss = v0.x*v0.x + v0.y*v0.y + v0.z*v0.z + v0.w*v0.w
                     + v1.x*v1.x + v1.y*v1.y + v1.z*v1.z + v1.w*v1.w;
#pragma unroll
            for (int o = 16; o > 0; o >>= 1) ss += __shfl_xor_sync(0xffffffffu, ss, o);

            float den = fmaxf(sqrtf(ss), EPSV);
            float inv = miss ? 0.0f : (1.0f / den);
            if (!miss) { nmW += 1.0f; wW += ss / (den * den); }

            acc0.x += v0.x * inv; acc0.y += v0.y * inv;
            acc0.z += v0.z * inv; acc0.w += v0.w * inv;
            acc1.x += v1.x * inv; acc1.y += v1.y * inv;
            acc1.z += v1.z * inv; acc1.w += v1.w * inv;
        }

        // per-warp column partials -> smem
        float* row = smf + w * 256;
        *(float4*)(row + lane * 4)       = acc0;
        *(float4*)(row + 128 + lane * 4) = acc1;
        if (lane == 0) { snm[w] = nmW; sww[w] = wW; }
        __syncthreads();

        // cross-warp column sum; write transposed partial
        float u = 0.0f;
#pragma unroll
        for (int ww = 0; ww < 8; ww++) u += smf[ww * 256 + tid];
        g_uT[(size_t)((mod << 8) + tid) * NRB + rb] = u;

        if (tid == 0) {
            float V = 0.0f, W = 0.0f;
#pragma unroll
            for (int i = 0; i < 8; i++) { V += snm[i]; W += sww[i]; }
            g_vw[blockIdx.x] = make_float2(V, W);
        }
    } else {
        // ================= cox block: 16 rows =================
        int cb = blockIdx.x - NPREP;
        int il = tid >> 4;
        int sub = tid & 15;
        int i = cb * 16 + il;
        int ti = t[i];
        float s = 0.0f;
        for (int j0 = 0; j0 < N_PAT; j0 += 1024) {
            __syncthreads();
            for (int j = tid; j < 1024; j += 256) {
                smi[j] = t[j0 + j];
                smf[j] = expf(h[j0 + j]);
            }
            __syncthreads();
#pragma unroll 8
            for (int j = sub; j < 1024; j += 16)
                if (ti == 0 || smi[j] >= ti) s += smf[j];
        }
#pragma unroll
        for (int o = 8; o > 0; o >>= 1) s += __shfl_xor_sync(0xffffffffu, s, o);
        if (sub == 0)
            g_coxpart[i] = e[i] ? (h[i] - logf(s)) : 0.0f;
    }
}

// ---------------- kernel 2: finish (fully parallel) ----------------
__global__ void __launch_bounds__(1024)
finish_kernel(const int* __restrict__ e, const int* __restrict__ mptr,
              float* __restrict__ out) {
    __shared__ float rv[1024];
    __shared__ float rw[1024];
    __shared__ float U2s[4], sV[4], sW[4];
    int tid = threadIdx.x;

    // 1) per-mod ||u||^2 : thread = (mod,col); 128 contiguous floats (32 x float4)
    {
        const float4* p4 = (const float4*)(g_uT + (size_t)tid * NRB);
        float u = 0.0f;
#pragma unroll
        for (int k = 0; k < NRB / 4; k++) {
            float4 v = p4[k];
            u += v.x + v.y + v.z + v.w;
        }
        rv[tid] = u * u;
    }
    __syncthreads();
#pragma unroll
    for (int o = 128; o > 0; o >>= 1) {
        if ((tid & 255) < o) rv[tid] += rv[tid + o];
        __syncthreads();
    }
    if (tid < 4) U2s[tid] = rv[tid << 8];
    __syncthreads();

    // 2) per-mod V, W (512 entries)
    {
        float V = 0.0f, W = 0.0f;
        if (tid < NPREP) { float2 vw = g_vw[tid]; V = vw.x; W = vw.y; }
        rv[tid] = V; rw[tid] = W;
    }
    __syncthreads();
#pragma unroll
    for (int o = NRB / 2; o > 0; o >>= 1) {
        if (tid < NPREP && (tid & (NRB - 1)) < o) {
            rv[tid] += rv[tid + o];
            rw[tid] += rw[tid + o];
        }
        __syncthreads();
    }
    if (tid < 4) { sV[tid] = rv[tid * NRB]; sW[tid] = rw[tid * NRB]; }
    __syncthreads();

    // 3) cox partial sum + event count
    {
        float cp = 0.0f, ef = 0.0f;
#pragma unroll
        for (int k = 0; k < N_PAT / 1024; k++) {
            int i = tid + k * 1024;
            cp += g_coxpart[i];
            ef += (float)e[i];
        }
        rv[tid] = cp; rw[tid] = ef;
    }
    __syncthreads();
#pragma unroll
    for (int o = 512; o > 0; o >>= 1) {
        if (tid < o) { rv[tid] += rv[tid + o]; rw[tid] += rw[tid + o]; }
        __syncthreads();
    }

    if (tid == 0) {
        int iv = mptr[0];
        float margin = (iv > -1000000 && iv < 1000000) ? (float)iv : __int_as_float(iv);

        double sim = (double)margin * (double)N_PAT * (double)(N_PAT - 1);
#pragma unroll
        for (int m = 0; m < 4; m++)
            sim += (double)sW[m] * (double)sV[m] - (double)U2s[m];
        double cox = -(double)rv[0] / (double)rw[0];
        out[0] = (float)(sim + cox);
    }
}

// ---------------- launch ----------------
extern "C" void kernel_launch(void* const* d_in, const int* in_sizes, int n_in,
                              void* d_out, int out_size) {
    const float* h   = (const float*)d_in[0];
    const int*   t   = (const int*)d_in[1];
    const int*   e   = (const int*)d_in[2];
    const float* eb0 = (const float*)d_in[3];
    const float* eb1 = (const float*)d_in[4];
    const float* eb2 = (const float*)d_in[5];
    const float* eb3 = (const float*)d_in[6];
    const int*   mg  = (const int*)d_in[7];
    float* out = (float*)d_out;

    main_kernel<<<NPREP + NCOX, 256>>>(h, t, e, eb0, eb1, eb2, eb3);
    finish_kernel<<<1, 1024>>>(e, mg, out);
}